// round 1
// baseline (speedup 1.0000x reference)
#include <cuda_runtime.h>

// Laplacian_Forward_Model: per-image 3x3 conv + two normalize passes + floor.
// One CTA per (image, mult-variant). 256 threads, 4 pixels/thread.
//
// Layout: input (B,1,32,32) f32; weight (n_mult,9); weight_factor (n_mult,1);
// output (n_mult,B,1,32,32) f32.

#define TPB 256
#define PITCH 34   // 34x34 zero-haloed tile

__global__ __launch_bounds__(TPB)
void lap_fwd_kernel(const float* __restrict__ in,
                    const float* __restrict__ weight,
                    const float* __restrict__ wfac,
                    float* __restrict__ out,
                    int B)
{
    __shared__ float img[PITCH * PITCH];   // padded tile, halo = 0
    __shared__ float rmin1[8], rmax1[8], rmin2[8], rmax2[8];

    const int tid  = threadIdx.x;
    const int lane = tid & 31;
    const int wid  = tid >> 5;
    const int b    = blockIdx.x;          // image index
    const int ii   = blockIdx.y;          // mult-variant index

    // ---- build the 3x3 kernel (broadcast, L1-cached) ----
    float wf = wfac[ii];
    wf = fminf(fmaxf(wf, 1.001f), 254.999f);
    float k[9];
#pragma unroll
    for (int j = 0; j < 9; ++j) {
        float w = weight[ii * 9 + j];
        w = fminf(fmaxf(w, -0.999f), 0.999f);
        k[j] = w * wf;
    }

    // ---- zero the halo ring (132 cells) ----
    // top & bottom rows: 2*34 = 68 ; left & right cols (rows 1..32): 2*32 = 64
    if (tid < 68) {
        int r = (tid < 34) ? 0 : 33;
        int c = (tid < 34) ? tid : tid - 34;
        img[r * PITCH + c] = 0.0f;
    } else if (tid < 132) {
        int t = tid - 68;                 // 0..63
        int r = (t & 31) + 1;             // 1..32
        int c = (t < 32) ? 0 : 33;
        img[r * PITCH + c] = 0.0f;
    }

    // ---- load 32x32 image with float4 (256 threads x 16B = 4KB) ----
    const float* src = in + (size_t)b * 1024;
    {
        float4 v = reinterpret_cast<const float4*>(src)[tid];
        int y = tid >> 3;                 // 0..31
        int x = (tid & 7) << 2;           // 0,4,...,28
        float* dst = &img[(y + 1) * PITCH + (x + 1)];
        dst[0] = v.x; dst[1] = v.y; dst[2] = v.z; dst[3] = v.w;
    }
    __syncthreads();

    // ---- 3x3 correlation for 4 pixels/thread ----
    float conv[4], xv[4];
#pragma unroll
    for (int q = 0; q < 4; ++q) {
        int p = tid + q * TPB;            // 0..1023
        int y = p >> 5;
        int x = p & 31;
        const float* c0 = &img[(y + 0) * PITCH + x];  // row y-1 of image (halo offset)
        const float* c1 = c0 + PITCH;
        const float* c2 = c1 + PITCH;
        float s;
        s  = k[0] * c0[0] + k[1] * c0[1] + k[2] * c0[2];
        s += k[3] * c1[0] + k[4] * c1[1] + k[5] * c1[2];
        s += k[6] * c2[0] + k[7] * c2[1] + k[8] * c2[2];
        conv[q] = s;
        xv[q]   = c1[1];                  // center pixel = original value
    }

    // ---- reduction 1: min/max of conv over the image ----
    float mn = fminf(fminf(conv[0], conv[1]), fminf(conv[2], conv[3]));
    float mx = fmaxf(fmaxf(conv[0], conv[1]), fmaxf(conv[2], conv[3]));
#pragma unroll
    for (int o = 16; o > 0; o >>= 1) {
        mn = fminf(mn, __shfl_xor_sync(0xffffffffu, mn, o));
        mx = fmaxf(mx, __shfl_xor_sync(0xffffffffu, mx, o));
    }
    if (lane == 0) { rmin1[wid] = mn; rmax1[wid] = mx; }
    __syncthreads();
    float cmin = rmin1[0], cmax = rmax1[0];
#pragma unroll
    for (int j = 1; j < 8; ++j) {
        cmin = fminf(cmin, rmin1[j]);
        cmax = fmaxf(cmax, rmax1[j]);
    }

    // ---- mod = (conv - cmin) / max(cmax-cmin, 1e-6) * 255 ; sharp = x + mod ----
    float den1 = fmaxf(cmax - cmin, 1e-6f);
    float sh[4];
#pragma unroll
    for (int q = 0; q < 4; ++q)
        sh[q] = xv[q] + __fdiv_rn(conv[q] - cmin, den1) * 255.0f;

    // ---- reduction 2: min/max of sharpened ----
    mn = fminf(fminf(sh[0], sh[1]), fminf(sh[2], sh[3]));
    mx = fmaxf(fmaxf(sh[0], sh[1]), fmaxf(sh[2], sh[3]));
#pragma unroll
    for (int o = 16; o > 0; o >>= 1) {
        mn = fminf(mn, __shfl_xor_sync(0xffffffffu, mn, o));
        mx = fmaxf(mx, __shfl_xor_sync(0xffffffffu, mx, o));
    }
    if (lane == 0) { rmin2[wid] = mn; rmax2[wid] = mx; }
    __syncthreads();
    float smin = rmin2[0], smax = rmax2[0];
#pragma unroll
    for (int j = 1; j < 8; ++j) {
        smin = fminf(smin, rmin2[j]);
        smax = fmaxf(smax, rmax2[j]);
    }

    // ---- res = clip((sh - smin)/clip(smax-smin,1e-6,255)*255, 0, 255); floor ----
    float den2 = fminf(fmaxf(smax - smin, 1e-6f), 255.0f);
    float* dst = out + ((size_t)ii * B + b) * 1024;
#pragma unroll
    for (int q = 0; q < 4; ++q) {
        float r = __fdiv_rn(sh[q] - smin, den2) * 255.0f;
        r = fminf(fmaxf(r, 0.0f), 255.0f);
        dst[tid + q * TPB] = floorf(r);
    }
}

extern "C" void kernel_launch(void* const* d_in, const int* in_sizes, int n_in,
                              void* d_out, int out_size)
{
    const float* in  = (const float*)d_in[0];
    const float* w   = (const float*)d_in[1];
    const float* wf  = (const float*)d_in[2];
    float* out       = (float*)d_out;

    int B      = in_sizes[0] / 1024;   // images
    int n_mult = in_sizes[1] / 9;      // mult variants

    dim3 grid(B, n_mult);
    lap_fwd_kernel<<<grid, TPB>>>(in, w, wf, out, B);
}

// round 4
// speedup vs baseline: 1.8288x; 1.8288x over previous
#include <cuda_runtime.h>

// Laplacian_Forward_Model: per-image 3x3 conv + two normalize passes + floor.
// One CTA per (image, mult-variant). 128 threads, 8 contiguous pixels/thread.
//
// input (B,1,32,32) f32; weight (n_mult,9); weight_factor (n_mult,1);
// output (n_mult,B,1,32,32) f32.

#define TPB   128
#define PITCH 36   // 34 rows x 36 cols; pitch 36 gives conflict-free LDS.128

__global__ __launch_bounds__(TPB)
void lap_fwd_kernel(const float* __restrict__ in,
                    const float* __restrict__ weight,
                    const float* __restrict__ wfac,
                    float* __restrict__ out,
                    int B)
{
    __shared__ float  img[PITCH * 34];
    __shared__ float2 red1[4], red2[4];

    const int tid  = threadIdx.x;
    const int lane = tid & 31;
    const int wrp  = tid >> 5;
    const int r    = tid >> 2;        // pixel row 0..31
    const int c    = tid & 3;         // col-group 0..3
    const int x0   = c << 3;          // 8c
    const int b    = blockIdx.x;
    const int ii   = blockIdx.y;
    const unsigned FULL = 0xffffffffu;

    // ---- 3x3 kernel (broadcast loads) ----
    float wf = fminf(fmaxf(wfac[ii], 1.001f), 254.999f);
    float k[9];
#pragma unroll
    for (int j = 0; j < 9; ++j) {
        float w = weight[ii * 9 + j];
        k[j] = fminf(fmaxf(w, -0.999f), 0.999f) * wf;
    }

    // ---- zero vertical halo rows 0 and 33 (cols 0..31) ----
    if (tid < 16) {
        int row = (tid < 8) ? 0 : 33;
        int col = (tid & 7) << 2;
        *reinterpret_cast<float4*>(&img[row * PITCH + col]) = make_float4(0.f, 0.f, 0.f, 0.f);
    }

    // ---- load 32x32 image: 256 float4, 2 per thread ----
    const float4* src = reinterpret_cast<const float4*>(in + (size_t)b * 1024);
#pragma unroll
    for (int q = 0; q < 2; ++q) {
        int i = tid + q * TPB;            // 0..255 (float4 index)
        float4 v = src[i];
        int y = i >> 3;                   // 0..31
        int x = (i & 7) << 2;
        *reinterpret_cast<float4*>(&img[(y + 1) * PITCH + x]) = v;
    }
    __syncthreads();

    // ---- 3x3 correlation, 8 pixels/thread, window via 2x LDS.128 + edge shfl ----
    float conv[8], xv[8];
#pragma unroll
    for (int j = 0; j < 8; ++j) conv[j] = 0.f;

#pragma unroll
    for (int t = 0; t < 3; ++t) {
        const float* row = &img[(r + t) * PITCH + x0];  // image row r-1+t (halo shift)
        float4 A = *reinterpret_cast<const float4*>(row);       // cols x0..x0+3
        float4 Bv = *reinterpret_cast<const float4*>(row + 4);  // cols x0+4..x0+7
        // left col x0-1 = neighbor (c-1)'s B.w ; right col x0+8 = neighbor (c+1)'s A.x
        float L = __shfl_up_sync(FULL, Bv.w, 1);
        float R = __shfl_down_sync(FULL, A.x, 1);
        if (c == 0) L = 0.f;
        if (c == 3) R = 0.f;
        float w[10] = {L, A.x, A.y, A.z, A.w, Bv.x, Bv.y, Bv.z, Bv.w, R};
        float k0 = k[3 * t], k1 = k[3 * t + 1], k2 = k[3 * t + 2];
#pragma unroll
        for (int j = 0; j < 8; ++j)
            conv[j] += k0 * w[j] + k1 * w[j + 1] + k2 * w[j + 2];
        if (t == 1) {
#pragma unroll
            for (int j = 0; j < 8; ++j) xv[j] = w[j + 1];   // original pixels
        }
    }

    // ---- reduction 1: min/max of conv over image ----
    float mn = conv[0], mx = conv[0];
#pragma unroll
    for (int j = 1; j < 8; ++j) { mn = fminf(mn, conv[j]); mx = fmaxf(mx, conv[j]); }
#pragma unroll
    for (int o = 16; o > 0; o >>= 1) {
        mn = fminf(mn, __shfl_xor_sync(FULL, mn, o));
        mx = fmaxf(mx, __shfl_xor_sync(FULL, mx, o));
    }
    if (lane == 0) red1[wrp] = make_float2(mn, mx);
    __syncthreads();
    float2 p0 = red1[0], p1 = red1[1], p2 = red1[2], p3 = red1[3];
    float cmin = fminf(fminf(p0.x, p1.x), fminf(p2.x, p3.x));
    float cmax = fmaxf(fmaxf(p0.y, p1.y), fmaxf(p2.y, p3.y));

    // ---- sharpen: sh = x + (conv - cmin) * (255/den1) ----
    float s1 = 255.0f / fmaxf(cmax - cmin, 1e-6f);   // block-uniform
    float sh[8];
#pragma unroll
    for (int j = 0; j < 8; ++j)
        sh[j] = xv[j] + (conv[j] - cmin) * s1;

    // ---- reduction 2: min/max of sharpened ----
    mn = sh[0]; mx = sh[0];
#pragma unroll
    for (int j = 1; j < 8; ++j) { mn = fminf(mn, sh[j]); mx = fmaxf(mx, sh[j]); }
#pragma unroll
    for (int o = 16; o > 0; o >>= 1) {
        mn = fminf(mn, __shfl_xor_sync(FULL, mn, o));
        mx = fmaxf(mx, __shfl_xor_sync(FULL, mx, o));
    }
    if (lane == 0) red2[wrp] = make_float2(mn, mx);
    __syncthreads();
    p0 = red2[0]; p1 = red2[1]; p2 = red2[2]; p3 = red2[3];
    float smin = fminf(fminf(p0.x, p1.x), fminf(p2.x, p3.x));
    float smax = fmaxf(fmaxf(p0.y, p1.y), fmaxf(p2.y, p3.y));

    // ---- final normalize + clamp + floor, store 2x float4 ----
    float s2 = 255.0f / fminf(fmaxf(smax - smin, 1e-6f), 255.0f);
    float* dst = out + ((size_t)ii * B + b) * 1024 + r * 32 + x0;
    float4 o0, o1;
    {
        float v[8];
#pragma unroll
        for (int j = 0; j < 8; ++j) {
            float rr = (sh[j] - smin) * s2;
            rr = fminf(fmaxf(rr, 0.0f), 255.0f);
            v[j] = floorf(rr);
        }
        o0 = make_float4(v[0], v[1], v[2], v[3]);
        o1 = make_float4(v[4], v[5], v[6], v[7]);
    }
    reinterpret_cast<float4*>(dst)[0] = o0;
    reinterpret_cast<float4*>(dst)[1] = o1;
}

extern "C" void kernel_launch(void* const* d_in, const int* in_sizes, int n_in,
                              void* d_out, int out_size)
{
    const float* in  = (const float*)d_in[0];
    const float* w   = (const float*)d_in[1];
    const float* wf  = (const float*)d_in[2];
    float* out       = (float*)d_out;

    int B      = in_sizes[0] / 1024;
    int n_mult = in_sizes[1] / 9;

    dim3 grid(B, n_mult);
    lap_fwd_kernel<<<grid, TPB>>>(in, w, wf, out, B);
}

// round 7
// speedup vs baseline: 1.8341x; 1.0029x over previous
#include <cuda_runtime.h>

// Laplacian_Forward_Model: per-image 3x3 conv + two normalize passes + floor.
// One CTA per (image, mult-variant). 128 threads, 8 contiguous pixels/thread.
//
// input (B,1,32,32) f32; weight (n_mult,9); weight_factor (n_mult,1);
// output (n_mult,B,1,32,32) f32.

#define TPB   128
#define PITCH 36   // 34 rows x 36 cols; pitch 36 -> conflict-free LDS.128

// Order-preserving float<->int map (self-inverse, monotone for all finite values):
//   key = bits ^ ((bits >> 31) & 0x7FFFFFFF)
__device__ __forceinline__ int f2ord(float x) {
    int b = __float_as_int(x);
    return b ^ ((b >> 31) & 0x7FFFFFFF);
}
__device__ __forceinline__ float ord2f(int k) {
    return __int_as_float(k ^ ((k >> 31) & 0x7FFFFFFF));
}

__global__ __launch_bounds__(TPB, 14)
void lap_fwd_kernel(const float* __restrict__ in,
                    const float* __restrict__ weight,
                    const float* __restrict__ wfac,
                    float* __restrict__ out,
                    int B)
{
    __shared__ float img[PITCH * 34];
    __shared__ __align__(16) int rmn1[4], rmx1[4], rmn2[4], rmx2[4];

    const int tid  = threadIdx.x;
    const int lane = tid & 31;
    const int wrp  = tid >> 5;
    const int r    = tid >> 2;        // pixel row 0..31
    const int c    = tid & 3;         // col-group 0..3
    const int x0   = c << 3;          // 8c
    const int b    = blockIdx.x;
    const int ii   = blockIdx.y;
    const unsigned FULL = 0xffffffffu;

    // ---- 3x3 kernel (broadcast loads) ----
    float wf = fminf(fmaxf(wfac[ii], 1.001f), 254.999f);
    float k[9];
#pragma unroll
    for (int j = 0; j < 9; ++j) {
        float w = weight[ii * 9 + j];
        k[j] = fminf(fmaxf(w, -0.999f), 0.999f) * wf;
    }

    // ---- zero vertical halo rows 0 and 33 (cols 0..31) ----
    if (tid < 16) {
        int row = (tid < 8) ? 0 : 33;
        int col = (tid & 7) << 2;
        *reinterpret_cast<float4*>(&img[row * PITCH + col]) = make_float4(0.f, 0.f, 0.f, 0.f);
    }

    // ---- load 32x32 image: 256 float4, 2 per thread ----
    const float4* src = reinterpret_cast<const float4*>(in + (size_t)b * 1024);
#pragma unroll
    for (int q = 0; q < 2; ++q) {
        int i = tid + q * TPB;            // float4 index 0..255
        float4 v = src[i];
        int y = i >> 3;
        int x = (i & 7) << 2;
        *reinterpret_cast<float4*>(&img[(y + 1) * PITCH + x]) = v;
    }
    __syncthreads();

    // ---- 3x3 correlation, 8 pixels/thread: 2x LDS.128 + edge shfl per row ----
    float conv[8];
#pragma unroll
    for (int j = 0; j < 8; ++j) conv[j] = 0.f;

#pragma unroll
    for (int t = 0; t < 3; ++t) {
        const float* row = &img[(r + t) * PITCH + x0];
        float4 A  = *reinterpret_cast<const float4*>(row);
        float4 Bv = *reinterpret_cast<const float4*>(row + 4);
        float L = __shfl_up_sync(FULL, Bv.w, 1);
        float R = __shfl_down_sync(FULL, A.x, 1);
        if (c == 0) L = 0.f;
        if (c == 3) R = 0.f;
        float w[10] = {L, A.x, A.y, A.z, A.w, Bv.x, Bv.y, Bv.z, Bv.w, R};
        float k0 = k[3 * t], k1 = k[3 * t + 1], k2 = k[3 * t + 2];
#pragma unroll
        for (int j = 0; j < 8; ++j)
            conv[j] += k0 * w[j] + k1 * w[j + 1] + k2 * w[j + 2];
    }

    // ---- reduction 1: min/max of conv (REDUX.S32 on order-mapped floats) ----
    float mn = conv[0], mx = conv[0];
#pragma unroll
    for (int j = 1; j < 8; ++j) { mn = fminf(mn, conv[j]); mx = fmaxf(mx, conv[j]); }
    int mni = __reduce_min_sync(FULL, f2ord(mn));
    int mxi = __reduce_max_sync(FULL, f2ord(mx));
    if (lane == 0) { rmn1[wrp] = mni; rmx1[wrp] = mxi; }
    __syncthreads();
    int4 m4 = *reinterpret_cast<int4*>(rmn1);
    int4 M4 = *reinterpret_cast<int4*>(rmx1);
    float cmin = ord2f(min(min(m4.x, m4.y), min(m4.z, m4.w)));
    float cmax = ord2f(max(max(M4.x, M4.y), max(M4.z, M4.w)));

    // ---- sharpen: sh = x + (conv - cmin) * (255/den1)  (x reloaded from smem) ----
    float s1 = 255.0f / fmaxf(cmax - cmin, 1e-6f);   // block-uniform
    float sh[8];
    {
        const float* row = &img[(r + 1) * PITCH + x0];
        float4 A  = *reinterpret_cast<const float4*>(row);
        float4 Bv = *reinterpret_cast<const float4*>(row + 4);
        float xv[8] = {A.x, A.y, A.z, A.w, Bv.x, Bv.y, Bv.z, Bv.w};
#pragma unroll
        for (int j = 0; j < 8; ++j)
            sh[j] = fmaf(conv[j] - cmin, s1, xv[j]);
    }

    // ---- reduction 2: min/max of sharpened ----
    mn = sh[0]; mx = sh[0];
#pragma unroll
    for (int j = 1; j < 8; ++j) { mn = fminf(mn, sh[j]); mx = fmaxf(mx, sh[j]); }
    mni = __reduce_min_sync(FULL, f2ord(mn));
    mxi = __reduce_max_sync(FULL, f2ord(mx));
    if (lane == 0) { rmn2[wrp] = mni; rmx2[wrp] = mxi; }
    __syncthreads();
    m4 = *reinterpret_cast<int4*>(rmn2);
    M4 = *reinterpret_cast<int4*>(rmx2);
    float smin = ord2f(min(min(m4.x, m4.y), min(m4.z, m4.w)));
    float smax = ord2f(max(max(M4.x, M4.y), max(M4.z, M4.w)));

    // ---- final: r = (sh - smin)*s2 -> clamp [0,255] -> floor, 2x STG.128 ----
    float s2 = 255.0f / fminf(fmaxf(smax - smin, 1e-6f), 255.0f);
    float d2 = -smin * s2;
    float* dst = out + ((size_t)ii * B + b) * 1024 + r * 32 + x0;
    float v[8];
#pragma unroll
    for (int j = 0; j < 8; ++j) {
        float rr = fmaf(sh[j], s2, d2);
        rr = fminf(fmaxf(rr, 0.0f), 255.0f);
        v[j] = floorf(rr);
    }
    reinterpret_cast<float4*>(dst)[0] = make_float4(v[0], v[1], v[2], v[3]);
    reinterpret_cast<float4*>(dst)[1] = make_float4(v[4], v[5], v[6], v[7]);
}

extern "C" void kernel_launch(void* const* d_in, const int* in_sizes, int n_in,
                              void* d_out, int out_size)
{
    const float* in  = (const float*)d_in[0];
    const float* w   = (const float*)d_in[1];
    const float* wf  = (const float*)d_in[2];
    float* out       = (float*)d_out;

    int B      = in_sizes[0] / 1024;
    int n_mult = in_sizes[1] / 9;

    dim3 grid(B, n_mult);
    lap_fwd_kernel<<<grid, TPB>>>(in, w, wf, out, B);
}